// round 14
// baseline (speedup 1.0000x reference)
#include <cuda_runtime.h>
#include <cuda_bf16.h>
#include <cuda_fp8.h>
#include <cstdint>

// ---------------------------------------------------------------------------
// SparseMemory read. Shapes: B=4, T=2048, S=4096, D=1024, TOPK=32. fp32 I/O.
//
// NUMERICS CONTRACT (validated rounds 6/7/9/10/13):
//  - Q/K projections: fp32 FFMA gemm_nt, per-element ascending-k chain FROZEN
//    (fp64 rescore ground truth). fp8 epilogue stores fused (post-accum).
//  - Scores GEMM: candidate nomination only -> fp8 e4m3 mma.sync (R14; bf16
//    mma.sync was throughput-bound at ~180 TF/s; tcgen05 unavailable at
//    compute_100 PTX target).
//  - V/O projections: split-bf16 (hi+lo, 3 MMA terms, fp32 accum).
//  - Selection: histogram-threshold pool (NCAND=128 superset; fp8 noise ~4.6
//    ranks, margin 96 ranks = ~15 sigma) -> exact fp64 rescore -> exact fp64
//    top-32 by rank (tie -> lower index). Output bits invariant.
// ---------------------------------------------------------------------------

#define BATCH   4
#define TQ      2048
#define SS      4096
#define DD      1024
#define TOPK    32
#define NCAND   128
#define MAXPOOL 224

#define MQ      (BATCH*TQ)      // 8192
#define MKV     (BATCH*SS)      // 16384

__device__ float g_Q  [8192u  * 1024u];
__device__ float g_K  [16384u * 1024u];
__device__ float g_V  [16384u * 1024u];
__device__ float g_S  [33554432u];
__device__ float g_CTX[8192u  * 1024u];
__device__ uint8_t g_Qf8[8192u  * 1024u];
__device__ uint8_t g_Kf8[16384u * 1024u];
__device__ __nv_bfloat16 g_Mh[16384u * 1024u];
__device__ __nv_bfloat16 g_Ml[16384u * 1024u];
__device__ __nv_bfloat16 g_Ch[8192u  * 1024u];
__device__ __nv_bfloat16 g_Cl[8192u  * 1024u];
__device__ __nv_bfloat16 g_Wh[1024u * 1024u];
__device__ __nv_bfloat16 g_Wl[1024u * 1024u];

__device__ __forceinline__ uint32_t pack4_e4m3(float x, float y, float z, float w)
{
    uint32_t a = __nv_cvt_float_to_fp8(x, __NV_SATFINITE, __NV_E4M3);
    uint32_t b = __nv_cvt_float_to_fp8(y, __NV_SATFINITE, __NV_E4M3);
    uint32_t c = __nv_cvt_float_to_fp8(z, __NV_SATFINITE, __NV_E4M3);
    uint32_t d = __nv_cvt_float_to_fp8(w, __NV_SATFINITE, __NV_E4M3);
    return a | (b << 8) | (c << 16) | (d << 24);
}

// ---------------------------------------------------------------------------
// fp32 tiled SGEMM (FROZEN accumulation; fused fp8 e4m3 output)
// ---------------------------------------------------------------------------
#define BM 128
#define BN 128
#define BK 16
#define TM 8
#define TN 8

__global__ __launch_bounds__(256, 2)
void gemm_nt(const float* __restrict__ A, const float* __restrict__ B,
             float* __restrict__ C, uint8_t* __restrict__ Cf8,
             const float* __restrict__ bias,
             int M, int N, int Kd, float alpha,
             long long strideA, long long strideB, long long strideC)
{
    __shared__ float As[2][BK][BM];
    __shared__ float Bs[2][BK][BN];

    const int bx = blockIdx.x;
    const int by = blockIdx.y;
    const int bz = blockIdx.z;

    A += bz * strideA + (long long)by * BM * Kd;
    B += bz * strideB + (long long)bx * BN * Kd;
    C += bz * strideC;
    if (Cf8) Cf8 += bz * strideC;

    const int tid  = threadIdx.x;
    const int tx   = tid & 15;
    const int ty   = tid >> 4;
    const int lrow = tid >> 2;
    const int lcol = (tid & 3) * 4;

    float acc[TM][TN];
    #pragma unroll
    for (int i = 0; i < TM; ++i)
        #pragma unroll
        for (int j = 0; j < TN; ++j) acc[i][j] = 0.f;

    float4 pa[2], pb[2];

    #pragma unroll
    for (int r = 0; r < 2; ++r) {
        pa[r] = *(const float4*)(A + (long long)(lrow + r * 64) * Kd + lcol);
        pb[r] = *(const float4*)(B + (long long)(lrow + r * 64) * Kd + lcol);
    }
    #pragma unroll
    for (int r = 0; r < 2; ++r) {
        int row = lrow + r * 64;
        As[0][lcol + 0][row] = pa[r].x;
        As[0][lcol + 1][row] = pa[r].y;
        As[0][lcol + 2][row] = pa[r].z;
        As[0][lcol + 3][row] = pa[r].w;
        Bs[0][lcol + 0][row] = pb[r].x;
        Bs[0][lcol + 1][row] = pb[r].y;
        Bs[0][lcol + 2][row] = pb[r].z;
        Bs[0][lcol + 3][row] = pb[r].w;
    }
    __syncthreads();

    int buf = 0;
    for (int k0 = 0; k0 < Kd; k0 += BK) {
        const int k1 = k0 + BK;
        const bool more = (k1 < Kd);

        if (more) {
            #pragma unroll
            for (int r = 0; r < 2; ++r) {
                pa[r] = *(const float4*)(A + (long long)(lrow + r * 64) * Kd + k1 + lcol);
                pb[r] = *(const float4*)(B + (long long)(lrow + r * 64) * Kd + k1 + lcol);
            }
        }

        #pragma unroll
        for (int kk = 0; kk < BK; ++kk) {
            float a[TM], b[TN];
            *(float4*)&a[0] = *(const float4*)&As[buf][kk][ty * TM];
            *(float4*)&a[4] = *(const float4*)&As[buf][kk][ty * TM + 4];
            *(float4*)&b[0] = *(const float4*)&Bs[buf][kk][tx * TN];
            *(float4*)&b[4] = *(const float4*)&Bs[buf][kk][tx * TN + 4];
            #pragma unroll
            for (int i = 0; i < TM; ++i)
                #pragma unroll
                for (int j = 0; j < TN; ++j)
                    acc[i][j] = fmaf(a[i], b[j], acc[i][j]);
        }

        if (more) {
            const int nb = buf ^ 1;
            #pragma unroll
            for (int r = 0; r < 2; ++r) {
                int row = lrow + r * 64;
                As[nb][lcol + 0][row] = pa[r].x;
                As[nb][lcol + 1][row] = pa[r].y;
                As[nb][lcol + 2][row] = pa[r].z;
                As[nb][lcol + 3][row] = pa[r].w;
                Bs[nb][lcol + 0][row] = pb[r].x;
                Bs[nb][lcol + 1][row] = pb[r].y;
                Bs[nb][lcol + 2][row] = pb[r].z;
                Bs[nb][lcol + 3][row] = pb[r].w;
            }
            __syncthreads();
            buf = nb;
        }
    }

    #pragma unroll
    for (int i = 0; i < TM; ++i) {
        int row = by * BM + ty * TM + i;
        float* crow = C + (long long)row * N;
        #pragma unroll
        for (int j4 = 0; j4 < TN; j4 += 4) {
            int col = bx * BN + tx * TN + j4;
            float4 o;
            o.x = acc[i][j4 + 0] * alpha;
            o.y = acc[i][j4 + 1] * alpha;
            o.z = acc[i][j4 + 2] * alpha;
            o.w = acc[i][j4 + 3] * alpha;
            if (bias) {
                float4 bb = *(const float4*)(bias + col);
                o.x += bb.x; o.y += bb.y; o.z += bb.z; o.w += bb.w;
            }
            *(float4*)(crow + col) = o;
            if (Cf8) {
                *(uint32_t*)(Cf8 + (long long)row * N + col) =
                    pack4_e4m3(o.x, o.y, o.z, o.w);
            }
        }
    }
}

// ---------------------------------------------------------------------------
// Conversions
// ---------------------------------------------------------------------------
__global__ __launch_bounds__(256)
void f32_split_bf16_kernel(const float* __restrict__ in,
                           __nv_bfloat16* __restrict__ hi,
                           __nv_bfloat16* __restrict__ lo, int n4)
{
    int i = blockIdx.x * blockDim.x + threadIdx.x;
    if (i < n4) {
        float4 v = ((const float4*)in)[i];
        __nv_bfloat16 hx = __float2bfloat16_rn(v.x);
        __nv_bfloat16 hy = __float2bfloat16_rn(v.y);
        __nv_bfloat16 hz = __float2bfloat16_rn(v.z);
        __nv_bfloat16 hw = __float2bfloat16_rn(v.w);
        __nv_bfloat16 lx = __float2bfloat16_rn(v.x - __bfloat162float(hx));
        __nv_bfloat16 ly = __float2bfloat16_rn(v.y - __bfloat162float(hy));
        __nv_bfloat16 lz = __float2bfloat16_rn(v.z - __bfloat162float(hz));
        __nv_bfloat16 lw = __float2bfloat16_rn(v.w - __bfloat162float(hw));
        ((__nv_bfloat162*)hi)[2 * i + 0] = __nv_bfloat162(hx, hy);
        ((__nv_bfloat162*)hi)[2 * i + 1] = __nv_bfloat162(hz, hw);
        ((__nv_bfloat162*)lo)[2 * i + 0] = __nv_bfloat162(lx, ly);
        ((__nv_bfloat162*)lo)[2 * i + 1] = __nv_bfloat162(lz, lw);
    }
}

// ---------------------------------------------------------------------------
// mma machinery
// ---------------------------------------------------------------------------
__device__ __forceinline__ uint32_t smem_u32p(const void* p) {
    return (uint32_t)__cvta_generic_to_shared(p);
}

__device__ __forceinline__ void ldsm_x4(uint32_t& r0, uint32_t& r1, uint32_t& r2, uint32_t& r3,
                                        uint32_t addr)
{
    asm volatile("ldmatrix.sync.aligned.m8n8.x4.shared.b16 {%0,%1,%2,%3}, [%4];"
                 : "=r"(r0), "=r"(r1), "=r"(r2), "=r"(r3) : "r"(addr));
}

__device__ __forceinline__ void mma_bf16(float* d, const uint32_t* a, uint32_t b0, uint32_t b1)
{
    asm volatile("mma.sync.aligned.m16n8k16.row.col.f32.bf16.bf16.f32 "
                 "{%0,%1,%2,%3}, {%4,%5,%6,%7}, {%8,%9}, {%0,%1,%2,%3};"
                 : "+f"(d[0]), "+f"(d[1]), "+f"(d[2]), "+f"(d[3])
                 : "r"(a[0]), "r"(a[1]), "r"(a[2]), "r"(a[3]), "r"(b0), "r"(b1));
}

__device__ __forceinline__ void mma_fp8(float* d, const uint32_t* a, uint32_t b0, uint32_t b1)
{
    asm volatile("mma.sync.aligned.m16n8k32.row.col.f32.e4m3.e4m3.f32 "
                 "{%0,%1,%2,%3}, {%4,%5,%6,%7}, {%8,%9}, {%0,%1,%2,%3};"
                 : "+f"(d[0]), "+f"(d[1]), "+f"(d[2]), "+f"(d[3])
                 : "r"(a[0]), "r"(a[1]), "r"(a[2]), "r"(a[3]), "r"(b0), "r"(b1));
}

// 64B rows (bf16 tiles): chunk' = c ^ ((r>>3)&... ) -- original bf16 swizzle
__device__ __forceinline__ int sw_off(int r, int c) {
    int phys = ((c ^ r) & 3) ^ ((r >> 2) & 1);
    return r * 64 + phys * 16;
}

// 64B rows (fp8 tiles): conflict-free for 8-row ldmatrix with 64B row stride
__device__ __forceinline__ int sw64(int r, int c) {
    return r * 64 + ((c ^ ((r >> 1) & 3)) & 3) * 16;
}

__device__ __forceinline__ void cp_async16(uint32_t saddr, const void* gptr)
{
    asm volatile("cp.async.ca.shared.global [%0], [%1], 16;"
                 :: "r"(saddr), "l"(gptr) : "memory");
}
__device__ __forceinline__ void cp_commit()
{
    asm volatile("cp.async.commit_group;" ::: "memory");
}
__device__ __forceinline__ void cp_wait2()
{
    asm volatile("cp.async.wait_group 2;" ::: "memory");
}

// ---------------------------------------------------------------------------
// fp8 e4m3 scores GEMM, cp.async 3-stage pipeline.
// S[b] = Qf8[b](2048x1024) x Kf8[b](4096x1024)^T * alpha, fp32 accum.
// CTA 128x128, BK=64 bytes (2 x k32 mma steps), 8 warps (4Mx2N), warp 32x64.
// Stage = A(8KB)+B(8KB); 3 stages = 48KB dynamic smem.
// ---------------------------------------------------------------------------
#define SF_STAGES 3
#define SF_STAGE_BYTES 16384
#define SF_NCHUNK (DD / 64)   // 16 k-chunks of 64 bytes

__global__ __launch_bounds__(256)
void gemm_nt_fp8_scores(const uint8_t* __restrict__ A,
                        const uint8_t* __restrict__ Bm,
                        float* __restrict__ C, float alpha)
{
    extern __shared__ __align__(16) char dsm[];

    const int bx = blockIdx.x;   // N tile (0..31)
    const int by = blockIdx.y;   // M tile (0..15)
    const int bz = blockIdx.z;   // batch

    const uint8_t* Ab = A  + (long long)bz * TQ * DD + (long long)by * 128 * DD;
    const uint8_t* Bb = Bm + (long long)bz * SS * DD + (long long)bx * 128 * DD;
    float* Cb = C + (long long)bz * TQ * SS;

    const int tid  = threadIdx.x;
    const int lane = tid & 31;
    const int wid  = tid >> 5;
    const int wm   = (wid & 3) * 32;
    const int wn   = (wid >> 2) * 64;

    // 512 16B-chunks per 8KB tile; each thread: 2 A + 2 B chunks
    const int r0 = tid >> 2,         c0 = tid & 3;
    const int r1 = (tid + 256) >> 2, c1 = (tid + 256) & 3;

    float acc[2][8][4];
    #pragma unroll
    for (int i = 0; i < 2; ++i)
        #pragma unroll
        for (int j = 0; j < 8; ++j)
            #pragma unroll
            for (int k = 0; k < 4; ++k) acc[i][j][k] = 0.f;

    auto issue = [&](int ck) {
        char* As = dsm + (ck % SF_STAGES) * SF_STAGE_BYTES;
        char* Bs = As + 8192;
        const int k0 = ck * 64;
        cp_async16(smem_u32p(As + sw64(r0, c0)), Ab + (long long)r0 * DD + k0 + c0 * 16);
        cp_async16(smem_u32p(As + sw64(r1, c1)), Ab + (long long)r1 * DD + k0 + c1 * 16);
        cp_async16(smem_u32p(Bs + sw64(r0, c0)), Bb + (long long)r0 * DD + k0 + c0 * 16);
        cp_async16(smem_u32p(Bs + sw64(r1, c1)), Bb + (long long)r1 * DD + k0 + c1 * 16);
    };

    #pragma unroll
    for (int s = 0; s < SF_STAGES; ++s) { issue(s); cp_commit(); }

    for (int ck = 0; ck < SF_NCHUNK; ++ck) {
        cp_wait2();
        __syncthreads();

        const char* As = dsm + (ck % SF_STAGES) * SF_STAGE_BYTES;
        const char* Bs = As + 8192;
        const uint32_t aBase = smem_u32p(As);
        const uint32_t bBase = smem_u32p(Bs);

        #pragma unroll
        for (int tk = 0; tk < 2; ++tk) {     // two k32 steps per 64B chunk
            uint32_t afrag[2][4];
            #pragma unroll
            for (int tm = 0; tm < 2; ++tm) {
                // x4 tiles: rows{0-7,8-15} x chunks{tk*2, tk*2+1}
                int r = wm + tm * 16 + (lane & 7) + ((lane >> 3) & 1) * 8;
                int c = tk * 2 + (lane >> 4);
                ldsm_x4(afrag[tm][0], afrag[tm][1], afrag[tm][2], afrag[tm][3],
                        aBase + sw64(r, c));
            }
            #pragma unroll
            for (int tn = 0; tn < 4; ++tn) {
                uint32_t bfrag[4];
                // x4 tiles: rows{0-7} x chunks{tk*2,tk*2+1}, rows{8-15} x same
                int r = wn + tn * 16 + (lane & 7) + ((lane >> 4) & 1) * 8;
                int c = tk * 2 + ((lane >> 3) & 1);
                ldsm_x4(bfrag[0], bfrag[1], bfrag[2], bfrag[3], bBase + sw64(r, c));
                #pragma unroll
                for (int tm = 0; tm < 2; ++tm) {
                    mma_fp8(acc[tm][tn * 2 + 0], afrag[tm], bfrag[0], bfrag[1]);
                    mma_fp8(acc[tm][tn * 2 + 1], afrag[tm], bfrag[2], bfrag[3]);
                }
            }
        }

        __syncthreads();
        if (ck + SF_STAGES < SF_NCHUNK) issue(ck + SF_STAGES);
        cp_commit();
    }

    #pragma unroll
    for (int tm = 0; tm < 2; ++tm) {
        #pragma unroll
        for (int t8 = 0; t8 < 8; ++t8) {
            int m = by * 128 + wm + tm * 16 + (lane >> 2);
            int n = bx * 128 + wn + t8 * 8 + (lane & 3) * 2;
            float2 lo = make_float2(acc[tm][t8][0] * alpha, acc[tm][t8][1] * alpha);
            float2 hi = make_float2(acc[tm][t8][2] * alpha, acc[tm][t8][3] * alpha);
            *(float2*)(Cb + (long long)m * SS + n)       = lo;
            *(float2*)(Cb + (long long)(m + 8) * SS + n) = hi;
        }
    }
}

// ---------------------------------------------------------------------------
// split-bf16 GEMM (V and O projections; values only). 32KB static smem.
// ---------------------------------------------------------------------------
__global__ __launch_bounds__(256)
void gemm_nt_bf16_split(const __nv_bfloat16* __restrict__ Ah,
                        const __nv_bfloat16* __restrict__ Al,
                        const __nv_bfloat16* __restrict__ Bh,
                        const __nv_bfloat16* __restrict__ Bl,
                        float* __restrict__ C, const float* __restrict__ bias)
{
    __shared__ __align__(16) char Ash[128 * 64];
    __shared__ __align__(16) char Asl[128 * 64];
    __shared__ __align__(16) char Bsh[128 * 64];
    __shared__ __align__(16) char Bsl[128 * 64];

    const int bx = blockIdx.x;
    const int by = blockIdx.y;

    const __nv_bfloat16* Ahb = Ah + (long long)by * 128 * DD;
    const __nv_bfloat16* Alb = Al + (long long)by * 128 * DD;
    const __nv_bfloat16* Bhb = Bh + (long long)bx * 128 * DD;
    const __nv_bfloat16* Blb = Bl + (long long)bx * 128 * DD;

    const int tid  = threadIdx.x;
    const int lane = tid & 31;
    const int wid  = tid >> 5;
    const int wm   = (wid & 3) * 32;
    const int wn   = (wid >> 2) * 64;

    const int r0 = tid >> 2,         c0 = tid & 3;
    const int r1 = (tid + 256) >> 2, c1 = (tid + 256) & 3;

    float acc[2][8][4];
    #pragma unroll
    for (int i = 0; i < 2; ++i)
        #pragma unroll
        for (int j = 0; j < 8; ++j)
            #pragma unroll
            for (int k = 0; k < 4; ++k) acc[i][j][k] = 0.f;

    for (int k0 = 0; k0 < DD; k0 += 32) {
        uint4 pah0 = *(const uint4*)(Ahb + (long long)r0 * DD + k0 + c0 * 8);
        uint4 pah1 = *(const uint4*)(Ahb + (long long)r1 * DD + k0 + c1 * 8);
        uint4 pal0 = *(const uint4*)(Alb + (long long)r0 * DD + k0 + c0 * 8);
        uint4 pal1 = *(const uint4*)(Alb + (long long)r1 * DD + k0 + c1 * 8);
        uint4 pbh0 = *(const uint4*)(Bhb + (long long)r0 * DD + k0 + c0 * 8);
        uint4 pbh1 = *(const uint4*)(Bhb + (long long)r1 * DD + k0 + c1 * 8);
        uint4 pbl0 = *(const uint4*)(Blb + (long long)r0 * DD + k0 + c0 * 8);
        uint4 pbl1 = *(const uint4*)(Blb + (long long)r1 * DD + k0 + c1 * 8);
        *(uint4*)(Ash + sw_off(r0, c0)) = pah0;
        *(uint4*)(Ash + sw_off(r1, c1)) = pah1;
        *(uint4*)(Asl + sw_off(r0, c0)) = pal0;
        *(uint4*)(Asl + sw_off(r1, c1)) = pal1;
        *(uint4*)(Bsh + sw_off(r0, c0)) = pbh0;
        *(uint4*)(Bsh + sw_off(r1, c1)) = pbh1;
        *(uint4*)(Bsl + sw_off(r0, c0)) = pbl0;
        *(uint4*)(Bsl + sw_off(r1, c1)) = pbl1;
        __syncthreads();

        const uint32_t ahB = smem_u32p(Ash);
        const uint32_t alB = smem_u32p(Asl);
        const uint32_t bhB = smem_u32p(Bsh);
        const uint32_t blB = smem_u32p(Bsl);

        #pragma unroll
        for (int tk = 0; tk < 2; ++tk) {
            uint32_t ah[2][4], al[2][4];
            #pragma unroll
            for (int tm = 0; tm < 2; ++tm) {
                int r = wm + tm * 16 + (lane & 7) + ((lane >> 3) & 1) * 8;
                int c = tk * 2 + (lane >> 4);
                ldsm_x4(ah[tm][0], ah[tm][1], ah[tm][2], ah[tm][3], ahB + sw_off(r, c));
                ldsm_x4(al[tm][0], al[tm][1], al[tm][2], al[tm][3], alB + sw_off(r, c));
            }
            #pragma unroll
            for (int tn = 0; tn < 4; ++tn) {
                uint32_t bh[4], bl[4];
                int r = wn + tn * 16 + (lane & 7) + ((lane >> 4) & 1) * 8;
                int c = tk * 2 + ((lane >> 3) & 1);
                ldsm_x4(bh[0], bh[1], bh[2], bh[3], bhB + sw_off(r, c));
                ldsm_x4(bl[0], bl[1], bl[2], bl[3], blB + sw_off(r, c));
                #pragma unroll
                for (int tm = 0; tm < 2; ++tm) {
                    mma_bf16(acc[tm][tn * 2 + 0], ah[tm], bh[0], bh[1]);
                    mma_bf16(acc[tm][tn * 2 + 1], ah[tm], bh[2], bh[3]);
                    mma_bf16(acc[tm][tn * 2 + 0], ah[tm], bl[0], bl[1]);
                    mma_bf16(acc[tm][tn * 2 + 1], ah[tm], bl[2], bl[3]);
                    mma_bf16(acc[tm][tn * 2 + 0], al[tm], bh[0], bh[1]);
                    mma_bf16(acc[tm][tn * 2 + 1], al[tm], bh[2], bh[3]);
                }
            }
        }
        __syncthreads();
    }

    #pragma unroll
    for (int tm = 0; tm < 2; ++tm) {
        #pragma unroll
        for (int t8 = 0; t8 < 8; ++t8) {
            int m = by * 128 + wm + tm * 16 + (lane >> 2);
            int n = bx * 128 + wn + t8 * 8 + (lane & 3) * 2;
            float2 bb = *(const float2*)(bias + n);
            float2 lo = make_float2(acc[tm][t8][0] + bb.x, acc[tm][t8][1] + bb.y);
            float2 hi = make_float2(acc[tm][t8][2] + bb.x, acc[tm][t8][3] + bb.y);
            *(float2*)(C + (long long)m * DD + n)       = lo;
            *(float2*)(C + (long long)(m + 8) * DD + n) = hi;
        }
    }
}

// ---------------------------------------------------------------------------
// top-k: histogram pool (NCAND=128 for fp8 noise) -> exact fp64 rescore ->
// fp64 top-32 by rank (tie -> lower index) -> softmax -> sparse AV.
// ---------------------------------------------------------------------------
#define NEG_HUGE_D (-1e300)
#define SCALE_D (0.03125)

__device__ __forceinline__ uint32_t mono_key(float s) {
    uint32_t u = __float_as_uint(s);
    return (u & 0x80000000u) ? ~u : (u | 0x80000000u);
}

__global__ __launch_bounds__(256)
void topk_softmax_av(const float* __restrict__ scores,
                     const float* __restrict__ Q,
                     const float* __restrict__ Km,
                     const float* __restrict__ V,
                     float* __restrict__ ctx)
{
    const int r = blockIdx.x;
    const int b = r >> 11;
    const int tid  = threadIdx.x;
    const int lane = tid & 31;
    const int wid  = tid >> 5;

    __shared__ float  sc[SS];
    __shared__ float  qrow[DD];
    __shared__ int    hist[256];
    __shared__ int    sBin1, sAbove1, sThresh16, sPCount;
    __shared__ int    pooli[MAXPOOL];
    __shared__ double cval[MAXPOOL];
    __shared__ float  selv[TOPK];
    __shared__ int    seli[TOPK];
    __shared__ float  prob[TOPK];

    const float* srow = scores + (long long)r * SS;
    for (int j = tid; j < SS; j += 256) sc[j] = srow[j];
    const float* qsrc = Q + (long long)r * DD;
    for (int j = tid; j < DD; j += 256) qrow[j] = qsrc[j];
    hist[tid] = 0;
    if (tid == 0) sPCount = 0;
    __syncthreads();

    const int base = tid * 16;
    uint32_t keys[16];
    #pragma unroll
    for (int j = 0; j < 16; ++j) {
        keys[j] = mono_key(sc[base + j]);
        atomicAdd(&hist[keys[j] >> 24], 1);
    }
    __syncthreads();

    if (tid == 0) {
        int acc = 0; int bbin = 255;
        for (; bbin >= 0; --bbin) {
            acc += hist[bbin];
            if (acc >= NCAND) break;
        }
        sBin1 = bbin;
        sAbove1 = acc - hist[bbin];
    }
    __syncthreads();
    const int bin1 = sBin1;
    const int above1 = sAbove1;
    hist[tid] = 0;
    __syncthreads();

    #pragma unroll
    for (int j = 0; j < 16; ++j) {
        if ((int)(keys[j] >> 24) == bin1)
            atomicAdd(&hist[(keys[j] >> 16) & 0xFF], 1);
    }
    __syncthreads();

    if (tid == 0) {
        int acc = above1; int bbin = 255;
        for (; bbin >= 0; --bbin) {
            acc += hist[bbin];
            if (acc >= NCAND) break;
        }
        sThresh16 = (bin1 << 8) | bbin;
    }
    __syncthreads();
    const uint32_t thresh16 = (uint32_t)sThresh16;

    #pragma unroll
    for (int j = 0; j < 16; ++j) {
        if ((keys[j] >> 16) >= thresh16) {
            int pos = atomicAdd(&sPCount, 1);
            if (pos < MAXPOOL) pooli[pos] = base + j;
        }
    }
    __syncthreads();
    const int pc = min(sPCount, MAXPOOL);

    const float* Kb = Km + (long long)b * SS * DD;
    for (int c = wid; c < pc; c += 8) {
        const int mi = pooli[c];
        const float* krow = Kb + (long long)mi * DD;
        double s = 0.0;
        #pragma unroll 8
        for (int i = 0; i < 32; ++i) {
            int d = lane + 32 * i;
            s += (double)qrow[d] * (double)krow[d];
        }
        #pragma unroll
        for (int off = 16; off > 0; off >>= 1)
            s += __shfl_xor_sync(0xffffffffu, s, off);
        if (lane == 0) cval[c] = s;
    }
    __syncthreads();

    if (tid < pc) {
        double v = cval[tid]; int ix = pooli[tid];
        int rank = 0;
        for (int j = 0; j < pc; ++j) {
            double vj = cval[j]; int ij = pooli[j];
            if (vj > v || (vj == v && ij < ix)) ++rank;
        }
        if (rank < TOPK) {
            selv[rank] = (float)(v * SCALE_D);
            seli[rank] = ix;
        }
    }
    __syncthreads();

    if (tid < 32) {
        float e = expf(selv[tid] - selv[0]);
        float s = e;
        #pragma unroll
        for (int off = 16; off > 0; off >>= 1)
            s += __shfl_xor_sync(0xffffffffu, s, off);
        prob[tid] = e / s;
    }
    __syncthreads();

    const float* Vb = V + (long long)b * SS * DD;
    const int d = tid * 4;
    float4 accv = make_float4(0.f, 0.f, 0.f, 0.f);
    #pragma unroll 4
    for (int i = 0; i < TOPK; ++i) {
        const float p = prob[i];
        float4 v = *(const float4*)(Vb + (long long)seli[i] * DD + d);
        accv.x = fmaf(p, v.x, accv.x);
        accv.y = fmaf(p, v.y, accv.y);
        accv.z = fmaf(p, v.z, accv.z);
        accv.w = fmaf(p, v.w, accv.w);
    }
    *(float4*)(ctx + (long long)r * DD + d) = accv;
}

// ---------------------------------------------------------------------------
// Launch
// ---------------------------------------------------------------------------
extern "C" void kernel_launch(void* const* d_in, const int* in_sizes, int n_in,
                              void* d_out, int out_size)
{
    const float* query = (const float*)d_in[0];
    const float* mem   = (const float*)d_in[1];
    const float* Wq = (const float*)d_in[3];
    const float* bq = (const float*)d_in[4];
    const float* Wk = (const float*)d_in[5];
    const float* bk = (const float*)d_in[6];
    const float* Wv = (const float*)d_in[7];
    const float* bv = (const float*)d_in[8];
    const float* Wo = (const float*)d_in[9];
    const float* bo = (const float*)d_in[10];
    float* out = (float*)d_out;

    float *Q, *K, *V, *S, *CTX;
    uint8_t *Qf8, *Kf8;
    __nv_bfloat16 *Mh, *Ml, *Ch, *Cl, *Wh, *Wl;
    cudaGetSymbolAddress((void**)&Q,   g_Q);
    cudaGetSymbolAddress((void**)&K,   g_K);
    cudaGetSymbolAddress((void**)&V,   g_V);
    cudaGetSymbolAddress((void**)&S,   g_S);
    cudaGetSymbolAddress((void**)&CTX, g_CTX);
    cudaGetSymbolAddress((void**)&Qf8, g_Qf8);
    cudaGetSymbolAddress((void**)&Kf8, g_Kf8);
    cudaGetSymbolAddress((void**)&Mh,  g_Mh);
    cudaGetSymbolAddress((void**)&Ml,  g_Ml);
    cudaGetSymbolAddress((void**)&Ch,  g_Ch);
    cudaGetSymbolAddress((void**)&Cl,  g_Cl);
    cudaGetSymbolAddress((void**)&Wh,  g_Wh);
    cudaGetSymbolAddress((void**)&Wl,  g_Wl);

    const float inv_sqrt_d = 1.0f / 32.0f;

    // Q/K projections (fp32, FROZEN chain) with fused fp8 e4m3 epilogue
    gemm_nt<<<dim3(DD / BN, MQ  / BM, 1), 256>>>(query, Wq, Q, Qf8, bq, MQ,  DD, DD, 1.f, 0, 0, 0);
    gemm_nt<<<dim3(DD / BN, MKV / BM, 1), 256>>>(mem,   Wk, K, Kf8, bk, MKV, DD, DD, 1.f, 0, 0, 0);

    // V projection via split-bf16 tensor cores (values only)
    f32_split_bf16_kernel<<<(MKV * DD / 4 + 255) / 256, 256>>>(mem, Mh, Ml, MKV * DD / 4);
    f32_split_bf16_kernel<<<(DD  * DD / 4 + 255) / 256, 256>>>(Wv,  Wh, Wl, DD  * DD / 4);
    gemm_nt_bf16_split<<<dim3(DD / 128, MKV / 128), 256>>>(Mh, Ml, Wh, Wl, V, bv);

    // Scores (candidate nomination): fp8 e4m3 mma.sync, cp.async pipeline
    gemm_nt_fp8_scores<<<dim3(SS / 128, TQ / 128, BATCH), 256,
                        SF_STAGES * SF_STAGE_BYTES>>>(Qf8, Kf8, S, inv_sqrt_d);

    // Histogram pool (128) -> exact fp64 rescore -> top-32 -> softmax -> AV
    topk_softmax_av<<<MQ, 256>>>(S, Q, K, V, CTX);

    // O projection via split-bf16 tensor cores (reuse weight split buffers)
    f32_split_bf16_kernel<<<(MQ * DD / 4 + 255) / 256, 256>>>(CTX, Ch, Cl, MQ * DD / 4);
    f32_split_bf16_kernel<<<(DD * DD / 4 + 255) / 256, 256>>>(Wo,  Wh, Wl, DD * DD / 4);
    gemm_nt_bf16_split<<<dim3(DD / 128, MQ / 128), 256>>>(Ch, Cl, Wh, Wl, out, bo);
}

// round 16
// speedup vs baseline: 1.1023x; 1.1023x over previous
#include <cuda_runtime.h>
#include <cuda_bf16.h>
#include <cstdint>

// ---------------------------------------------------------------------------
// SparseMemory read. Shapes: B=4, T=2048, S=4096, D=1024, TOPK=32. fp32 I/O.
//
// NUMERICS CONTRACT (validated rounds 6/7/9/10/13/14):
//  - Q/K projections: fp32 FFMA gemm_nt; per-element ascending-k fmaf chain
//    FROZEN (fp64 rescore ground truth). R16: register-pipelined fragments
//    (schedule-only change; chain order and q,k bits identical).
//  - Scores GEMM: candidate nomination only -> bf16 mma.sync (R10 kernel;
//    fp8 regressed in R14, tcgen05 unavailable at compute_100).
//  - V/O projections: split-bf16 (hi+lo, 3 MMA terms, fp32 accum).
//  - Selection: histogram-threshold pool (NCAND=48 superset) -> exact fp64
//    rescore -> exact fp64 top-32 by rank (tie -> lower index).
//
// R16 = R15 resubmitted unchanged (R15 was a broker flake).
// ---------------------------------------------------------------------------

#define BATCH   4
#define TQ      2048
#define SS      4096
#define DD      1024
#define TOPK    32
#define NCAND   48
#define MAXPOOL 128

#define MQ      (BATCH*TQ)      // 8192
#define MKV     (BATCH*SS)      // 16384

__device__ float g_Q  [8192u  * 1024u];
__device__ float g_K  [16384u * 1024u];
__device__ float g_V  [16384u * 1024u];
__device__ float g_S  [33554432u];
__device__ float g_CTX[8192u  * 1024u];
__device__ __nv_bfloat16 g_Qh[8192u  * 1024u];
__device__ __nv_bfloat16 g_Kh[16384u * 1024u];
__device__ __nv_bfloat16 g_Mh[16384u * 1024u];
__device__ __nv_bfloat16 g_Ml[16384u * 1024u];
__device__ __nv_bfloat16 g_Ch[8192u  * 1024u];
__device__ __nv_bfloat16 g_Cl[8192u  * 1024u];
__device__ __nv_bfloat16 g_Wh[1024u * 1024u];
__device__ __nv_bfloat16 g_Wl[1024u * 1024u];

// ---------------------------------------------------------------------------
// fp32 tiled SGEMM (FROZEN fmaf chain; fused bf16 output).
// Software-pipelined smem fragments (af/bf double buffer across kk).
// ---------------------------------------------------------------------------
#define BM 128
#define BN 128
#define BK 16
#define TM 8
#define TN 8

__global__ __launch_bounds__(256, 2)
void gemm_nt(const float* __restrict__ A, const float* __restrict__ B,
             float* __restrict__ C, __nv_bfloat16* __restrict__ Cbf,
             const float* __restrict__ bias,
             int M, int N, int Kd, float alpha,
             long long strideA, long long strideB, long long strideC)
{
    __shared__ float As[2][BK][BM];
    __shared__ float Bs[2][BK][BN];

    const int bx = blockIdx.x;
    const int by = blockIdx.y;
    const int bz = blockIdx.z;

    A += bz * strideA + (long long)by * BM * Kd;
    B += bz * strideB + (long long)bx * BN * Kd;
    C += bz * strideC;
    if (Cbf) Cbf += bz * strideC;

    const int tid  = threadIdx.x;
    const int tx   = tid & 15;
    const int ty   = tid >> 4;
    const int lrow = tid >> 2;
    const int lcol = (tid & 3) * 4;

    float acc[TM][TN];
    #pragma unroll
    for (int i = 0; i < TM; ++i)
        #pragma unroll
        for (int j = 0; j < TN; ++j) acc[i][j] = 0.f;

    float4 pa[2], pb[2];

    #pragma unroll
    for (int r = 0; r < 2; ++r) {
        pa[r] = *(const float4*)(A + (long long)(lrow + r * 64) * Kd + lcol);
        pb[r] = *(const float4*)(B + (long long)(lrow + r * 64) * Kd + lcol);
    }
    #pragma unroll
    for (int r = 0; r < 2; ++r) {
        int row = lrow + r * 64;
        As[0][lcol + 0][row] = pa[r].x;
        As[0][lcol + 1][row] = pa[r].y;
        As[0][lcol + 2][row] = pa[r].z;
        As[0][lcol + 3][row] = pa[r].w;
        Bs[0][lcol + 0][row] = pb[r].x;
        Bs[0][lcol + 1][row] = pb[r].y;
        Bs[0][lcol + 2][row] = pb[r].z;
        Bs[0][lcol + 3][row] = pb[r].w;
    }
    __syncthreads();

    float af[2][TM], bf[2][TN];

    int buf = 0;
    for (int k0 = 0; k0 < Kd; k0 += BK) {
        const int k1 = k0 + BK;
        const bool more = (k1 < Kd);

        if (more) {
            #pragma unroll
            for (int r = 0; r < 2; ++r) {
                pa[r] = *(const float4*)(A + (long long)(lrow + r * 64) * Kd + k1 + lcol);
                pb[r] = *(const float4*)(B + (long long)(lrow + r * 64) * Kd + k1 + lcol);
            }
        }

        // preload kk=0 fragments
        *(float4*)&af[0][0] = *(const float4*)&As[buf][0][ty * TM];
        *(float4*)&af[0][4] = *(const float4*)&As[buf][0][ty * TM + 4];
        *(float4*)&bf[0][0] = *(const float4*)&Bs[buf][0][tx * TN];
        *(float4*)&bf[0][4] = *(const float4*)&Bs[buf][0][tx * TN + 4];

        #pragma unroll
        for (int kk = 0; kk < BK; ++kk) {
            const int cur = kk & 1;
            const int nxt = cur ^ 1;
            if (kk + 1 < BK) {
                *(float4*)&af[nxt][0] = *(const float4*)&As[buf][kk + 1][ty * TM];
                *(float4*)&af[nxt][4] = *(const float4*)&As[buf][kk + 1][ty * TM + 4];
                *(float4*)&bf[nxt][0] = *(const float4*)&Bs[buf][kk + 1][tx * TN];
                *(float4*)&bf[nxt][4] = *(const float4*)&Bs[buf][kk + 1][tx * TN + 4];
            }
            #pragma unroll
            for (int i = 0; i < TM; ++i)
                #pragma unroll
                for (int j = 0; j < TN; ++j)
                    acc[i][j] = fmaf(af[cur][i], bf[cur][j], acc[i][j]);
        }

        if (more) {
            const int nb = buf ^ 1;
            #pragma unroll
            for (int r = 0; r < 2; ++r) {
                int row = lrow + r * 64;
                As[nb][lcol + 0][row] = pa[r].x;
                As[nb][lcol + 1][row] = pa[r].y;
                As[nb][lcol + 2][row] = pa[r].z;
                As[nb][lcol + 3][row] = pa[r].w;
                Bs[nb][lcol + 0][row] = pb[r].x;
                Bs[nb][lcol + 1][row] = pb[r].y;
                Bs[nb][lcol + 2][row] = pb[r].z;
                Bs[nb][lcol + 3][row] = pb[r].w;
            }
            __syncthreads();
            buf = nb;
        }
    }

    #pragma unroll
    for (int i = 0; i < TM; ++i) {
        int row = by * BM + ty * TM + i;
        float* crow = C + (long long)row * N;
        #pragma unroll
        for (int j4 = 0; j4 < TN; j4 += 4) {
            int col = bx * BN + tx * TN + j4;
            float4 o;
            o.x = acc[i][j4 + 0] * alpha;
            o.y = acc[i][j4 + 1] * alpha;
            o.z = acc[i][j4 + 2] * alpha;
            o.w = acc[i][j4 + 3] * alpha;
            if (bias) {
                float4 bb = *(const float4*)(bias + col);
                o.x += bb.x; o.y += bb.y; o.z += bb.z; o.w += bb.w;
            }
            *(float4*)(crow + col) = o;
            if (Cbf) {
                __nv_bfloat162* brow = (__nv_bfloat162*)(Cbf + (long long)row * N + col);
                brow[0] = __floats2bfloat162_rn(o.x, o.y);
                brow[1] = __floats2bfloat162_rn(o.z, o.w);
            }
        }
    }
}

// ---------------------------------------------------------------------------
// Conversions
// ---------------------------------------------------------------------------
__global__ __launch_bounds__(256)
void f32_split_bf16_kernel(const float* __restrict__ in,
                           __nv_bfloat16* __restrict__ hi,
                           __nv_bfloat16* __restrict__ lo, int n4)
{
    int i = blockIdx.x * blockDim.x + threadIdx.x;
    if (i < n4) {
        float4 v = ((const float4*)in)[i];
        __nv_bfloat16 hx = __float2bfloat16_rn(v.x);
        __nv_bfloat16 hy = __float2bfloat16_rn(v.y);
        __nv_bfloat16 hz = __float2bfloat16_rn(v.z);
        __nv_bfloat16 hw = __float2bfloat16_rn(v.w);
        __nv_bfloat16 lx = __float2bfloat16_rn(v.x - __bfloat162float(hx));
        __nv_bfloat16 ly = __float2bfloat16_rn(v.y - __bfloat162float(hy));
        __nv_bfloat16 lz = __float2bfloat16_rn(v.z - __bfloat162float(hz));
        __nv_bfloat16 lw = __float2bfloat16_rn(v.w - __bfloat162float(hw));
        ((__nv_bfloat162*)hi)[2 * i + 0] = __nv_bfloat162(hx, hy);
        ((__nv_bfloat162*)hi)[2 * i + 1] = __nv_bfloat162(hz, hw);
        ((__nv_bfloat162*)lo)[2 * i + 0] = __nv_bfloat162(lx, ly);
        ((__nv_bfloat162*)lo)[2 * i + 1] = __nv_bfloat162(lz, lw);
    }
}

// ---------------------------------------------------------------------------
// mma.sync machinery
// ---------------------------------------------------------------------------
__device__ __forceinline__ uint32_t smem_u32p(const void* p) {
    return (uint32_t)__cvta_generic_to_shared(p);
}

__device__ __forceinline__ void ldsm_x4(uint32_t& r0, uint32_t& r1, uint32_t& r2, uint32_t& r3,
                                        uint32_t addr)
{
    asm volatile("ldmatrix.sync.aligned.m8n8.x4.shared.b16 {%0,%1,%2,%3}, [%4];"
                 : "=r"(r0), "=r"(r1), "=r"(r2), "=r"(r3) : "r"(addr));
}

__device__ __forceinline__ void mma_bf16(float* d, const uint32_t* a, uint32_t b0, uint32_t b1)
{
    asm volatile("mma.sync.aligned.m16n8k16.row.col.f32.bf16.bf16.f32 "
                 "{%0,%1,%2,%3}, {%4,%5,%6,%7}, {%8,%9}, {%0,%1,%2,%3};"
                 : "+f"(d[0]), "+f"(d[1]), "+f"(d[2]), "+f"(d[3])
                 : "r"(a[0]), "r"(a[1]), "r"(a[2]), "r"(a[3]), "r"(b0), "r"(b1));
}

__device__ __forceinline__ int sw_off(int r, int c) {
    int phys = ((c ^ r) & 3) ^ ((r >> 2) & 1);
    return r * 64 + phys * 16;
}

// ---------------------------------------------------------------------------
// bf16 scores GEMM (validated R10 config; 32KB static smem, reg prefetch)
// ---------------------------------------------------------------------------
__global__ __launch_bounds__(256)
void gemm_nt_bf16_scores(const __nv_bfloat16* __restrict__ A,
                         const __nv_bfloat16* __restrict__ Bm,
                         float* __restrict__ C, float alpha)
{
    __shared__ __align__(16) char As[2][128 * 64];
    __shared__ __align__(16) char Bs[2][128 * 64];

    const int bx = blockIdx.x;
    const int by = blockIdx.y;
    const int bz = blockIdx.z;

    const __nv_bfloat16* Ab = A  + (long long)bz * TQ * DD + (long long)by * 128 * DD;
    const __nv_bfloat16* Bb = Bm + (long long)bz * SS * DD + (long long)bx * 128 * DD;
    float* Cb = C + (long long)bz * TQ * SS;

    const int tid  = threadIdx.x;
    const int lane = tid & 31;
    const int wid  = tid >> 5;
    const int wm   = (wid & 3) * 32;
    const int wn   = (wid >> 2) * 64;

    const int r0 = tid >> 2,         c0 = tid & 3;
    const int r1 = (tid + 256) >> 2, c1 = (tid + 256) & 3;

    float acc[2][8][4];
    #pragma unroll
    for (int i = 0; i < 2; ++i)
        #pragma unroll
        for (int j = 0; j < 8; ++j)
            #pragma unroll
            for (int k = 0; k < 4; ++k) acc[i][j][k] = 0.f;

    uint4 pa0, pa1, pb0, pb1;

    pa0 = *(const uint4*)(Ab + (long long)r0 * DD + c0 * 8);
    pa1 = *(const uint4*)(Ab + (long long)r1 * DD + c1 * 8);
    pb0 = *(const uint4*)(Bb + (long long)r0 * DD + c0 * 8);
    pb1 = *(const uint4*)(Bb + (long long)r1 * DD + c1 * 8);
    *(uint4*)(As[0] + sw_off(r0, c0)) = pa0;
    *(uint4*)(As[0] + sw_off(r1, c1)) = pa1;
    *(uint4*)(Bs[0] + sw_off(r0, c0)) = pb0;
    *(uint4*)(Bs[0] + sw_off(r1, c1)) = pb1;
    __syncthreads();

    int buf = 0;
    for (int k0 = 0; k0 < DD; k0 += 32) {
        const int k1 = k0 + 32;
        const bool more = (k1 < DD);

        if (more) {
            pa0 = *(const uint4*)(Ab + (long long)r0 * DD + k1 + c0 * 8);
            pa1 = *(const uint4*)(Ab + (long long)r1 * DD + k1 + c1 * 8);
            pb0 = *(const uint4*)(Bb + (long long)r0 * DD + k1 + c0 * 8);
            pb1 = *(const uint4*)(Bb + (long long)r1 * DD + k1 + c1 * 8);
        }

        const uint32_t aBase = smem_u32p(As[buf]);
        const uint32_t bBase = smem_u32p(Bs[buf]);

        #pragma unroll
        for (int tk = 0; tk < 2; ++tk) {
            uint32_t afrag[2][4];
            #pragma unroll
            for (int tm = 0; tm < 2; ++tm) {
                int r = wm + tm * 16 + (lane & 7) + ((lane >> 3) & 1) * 8;
                int c = tk * 2 + (lane >> 4);
                ldsm_x4(afrag[tm][0], afrag[tm][1], afrag[tm][2], afrag[tm][3],
                        aBase + sw_off(r, c));
            }
            #pragma unroll
            for (int tn = 0; tn < 4; ++tn) {
                uint32_t bfrag[4];
                int r = wn + tn * 16 + (lane & 7) + ((lane >> 4) & 1) * 8;
                int c = tk * 2 + ((lane >> 3) & 1);
                ldsm_x4(bfrag[0], bfrag[1], bfrag[2], bfrag[3], bBase + sw_off(r, c));
                #pragma unroll
                for (int tm = 0; tm < 2; ++tm) {
                    mma_bf16(acc[tm][tn * 2 + 0], afrag[tm], bfrag[0], bfrag[1]);
                    mma_bf16(acc[tm][tn * 2 + 1], afrag[tm], bfrag[2], bfrag[3]);
                }
            }
        }

        if (more) {
            const int nb = buf ^ 1;
            *(uint4*)(As[nb] + sw_off(r0, c0)) = pa0;
            *(uint4*)(As[nb] + sw_off(r1, c1)) = pa1;
            *(uint4*)(Bs[nb] + sw_off(r0, c0)) = pb0;
            *(uint4*)(Bs[nb] + sw_off(r1, c1)) = pb1;
            __syncthreads();
            buf = nb;
        }
    }

    #pragma unroll
    for (int tm = 0; tm < 2; ++tm) {
        #pragma unroll
        for (int t8 = 0; t8 < 8; ++t8) {
            int m = by * 128 + wm + tm * 16 + (lane >> 2);
            int n = bx * 128 + wn + t8 * 8 + (lane & 3) * 2;
            float2 lo = make_float2(acc[tm][t8][0] * alpha, acc[tm][t8][1] * alpha);
            float2 hi = make_float2(acc[tm][t8][2] * alpha, acc[tm][t8][3] * alpha);
            *(float2*)(Cb + (long long)m * SS + n)       = lo;
            *(float2*)(Cb + (long long)(m + 8) * SS + n) = hi;
        }
    }
}

// ---------------------------------------------------------------------------
// split-bf16 GEMM (V and O projections; values only). 32KB static smem.
// ---------------------------------------------------------------------------
__global__ __launch_bounds__(256)
void gemm_nt_bf16_split(const __nv_bfloat16* __restrict__ Ah,
                        const __nv_bfloat16* __restrict__ Al,
                        const __nv_bfloat16* __restrict__ Bh,
                        const __nv_bfloat16* __restrict__ Bl,
                        float* __restrict__ C, const float* __restrict__ bias)
{
    __shared__ __align__(16) char Ash[128 * 64];
    __shared__ __align__(16) char Asl[128 * 64];
    __shared__ __align__(16) char Bsh[128 * 64];
    __shared__ __align__(16) char Bsl[128 * 64];

    const int bx = blockIdx.x;
    const int by = blockIdx.y;

    const __nv_bfloat16* Ahb = Ah + (long long)by * 128 * DD;
    const __nv_bfloat16* Alb = Al + (long long)by * 128 * DD;
    const __nv_bfloat16* Bhb = Bh + (long long)bx * 128 * DD;
    const __nv_bfloat16* Blb = Bl + (long long)bx * 128 * DD;

    const int tid  = threadIdx.x;
    const int lane = tid & 31;
    const int wid  = tid >> 5;
    const int wm   = (wid & 3) * 32;
    const int wn   = (wid >> 2) * 64;

    const int r0 = tid >> 2,         c0 = tid & 3;
    const int r1 = (tid + 256) >> 2, c1 = (tid + 256) & 3;

    float acc[2][8][4];
    #pragma unroll
    for (int i = 0; i < 2; ++i)
        #pragma unroll
        for (int j = 0; j < 8; ++j)
            #pragma unroll
            for (int k = 0; k < 4; ++k) acc[i][j][k] = 0.f;

    for (int k0 = 0; k0 < DD; k0 += 32) {
        uint4 pah0 = *(const uint4*)(Ahb + (long long)r0 * DD + k0 + c0 * 8);
        uint4 pah1 = *(const uint4*)(Ahb + (long long)r1 * DD + k0 + c1 * 8);
        uint4 pal0 = *(const uint4*)(Alb + (long long)r0 * DD + k0 + c0 * 8);
        uint4 pal1 = *(const uint4*)(Alb + (long long)r1 * DD + k0 + c1 * 8);
        uint4 pbh0 = *(const uint4*)(Bhb + (long long)r0 * DD + k0 + c0 * 8);
        uint4 pbh1 = *(const uint4*)(Bhb + (long long)r1 * DD + k0 + c1 * 8);
        uint4 pbl0 = *(const uint4*)(Blb + (long long)r0 * DD + k0 + c0 * 8);
        uint4 pbl1 = *(const uint4*)(Blb + (long long)r1 * DD + k0 + c1 * 8);
        *(uint4*)(Ash + sw_off(r0, c0)) = pah0;
        *(uint4*)(Ash + sw_off(r1, c1)) = pah1;
        *(uint4*)(Asl + sw_off(r0, c0)) = pal0;
        *(uint4*)(Asl + sw_off(r1, c1)) = pal1;
        *(uint4*)(Bsh + sw_off(r0, c0)) = pbh0;
        *(uint4*)(Bsh + sw_off(r1, c1)) = pbh1;
        *(uint4*)(Bsl + sw_off(r0, c0)) = pbl0;
        *(uint4*)(Bsl + sw_off(r1, c1)) = pbl1;
        __syncthreads();

        const uint32_t ahB = smem_u32p(Ash);
        const uint32_t alB = smem_u32p(Asl);
        const uint32_t bhB = smem_u32p(Bsh);
        const uint32_t blB = smem_u32p(Bsl);

        #pragma unroll
        for (int tk = 0; tk < 2; ++tk) {
            uint32_t ah[2][4], al[2][4];
            #pragma unroll
            for (int tm = 0; tm < 2; ++tm) {
                int r = wm + tm * 16 + (lane & 7) + ((lane >> 3) & 1) * 8;
                int c = tk * 2 + (lane >> 4);
                ldsm_x4(ah[tm][0], ah[tm][1], ah[tm][2], ah[tm][3], ahB + sw_off(r, c));
                ldsm_x4(al[tm][0], al[tm][1], al[tm][2], al[tm][3], alB + sw_off(r, c));
            }
            #pragma unroll
            for (int tn = 0; tn < 4; ++tn) {
                uint32_t bh[4], bl[4];
                int r = wn + tn * 16 + (lane & 7) + ((lane >> 4) & 1) * 8;
                int c = tk * 2 + ((lane >> 3) & 1);
                ldsm_x4(bh[0], bh[1], bh[2], bh[3], bhB + sw_off(r, c));
                ldsm_x4(bl[0], bl[1], bl[2], bl[3], blB + sw_off(r, c));
                #pragma unroll
                for (int tm = 0; tm < 2; ++tm) {
                    mma_bf16(acc[tm][tn * 2 + 0], ah[tm], bh[0], bh[1]);
                    mma_bf16(acc[tm][tn * 2 + 1], ah[tm], bh[2], bh[3]);
                    mma_bf16(acc[tm][tn * 2 + 0], ah[tm], bl[0], bl[1]);
                    mma_bf16(acc[tm][tn * 2 + 1], ah[tm], bl[2], bl[3]);
                    mma_bf16(acc[tm][tn * 2 + 0], al[tm], bh[0], bh[1]);
                    mma_bf16(acc[tm][tn * 2 + 1], al[tm], bh[2], bh[3]);
                }
            }
        }
        __syncthreads();
    }

    #pragma unroll
    for (int tm = 0; tm < 2; ++tm) {
        #pragma unroll
        for (int t8 = 0; t8 < 8; ++t8) {
            int m = by * 128 + wm + tm * 16 + (lane >> 2);
            int n = bx * 128 + wn + t8 * 8 + (lane & 3) * 2;
            float2 bb = *(const float2*)(bias + n);
            float2 lo = make_float2(acc[tm][t8][0] + bb.x, acc[tm][t8][1] + bb.y);
            float2 hi = make_float2(acc[tm][t8][2] + bb.x, acc[tm][t8][3] + bb.y);
            *(float2*)(C + (long long)m * DD + n)       = lo;
            *(float2*)(C + (long long)(m + 8) * DD + n) = hi;
        }
    }
}

// ---------------------------------------------------------------------------
// top-k: histogram pool -> exact fp64 rescore -> fp64 top-32 by rank
// (validated round 10 — unchanged, NCAND=48)
// ---------------------------------------------------------------------------
#define NEG_HUGE_D (-1e300)
#define SCALE_D (0.03125)

__device__ __forceinline__ uint32_t mono_key(float s) {
    uint32_t u = __float_as_uint(s);
    return (u & 0x80000000u) ? ~u : (u | 0x80000000u);
}

__global__ __launch_bounds__(256)
void topk_softmax_av(const float* __restrict__ scores,
                     const float* __restrict__ Q,
                     const float* __restrict__ Km,
                     const float* __restrict__ V,
                     float* __restrict__ ctx)
{
    const int r = blockIdx.x;
    const int b = r >> 11;
    const int tid  = threadIdx.x;
    const int lane = tid & 31;
    const int wid  = tid >> 5;

    __shared__ float  sc[SS];
    __shared__ float  qrow[DD];
    __shared__ int    hist[256];
    __shared__ int    sBin1, sAbove1, sThresh16, sPCount;
    __shared__ int    pooli[MAXPOOL];
    __shared__ double cval[MAXPOOL];
    __shared__ float  selv[TOPK];
    __shared__ int    seli[TOPK];
    __shared__ float  prob[TOPK];

    const float* srow = scores + (long long)r * SS;
    for (int j = tid; j < SS; j += 256) sc[j] = srow[j];
    const float* qsrc = Q + (long long)r * DD;
    for (int j = tid; j < DD; j += 256) qrow[j] = qsrc[j];
    hist[tid] = 0;
    if (tid == 0) sPCount = 0;
    __syncthreads();

    const int base = tid * 16;
    uint32_t keys[16];
    #pragma unroll
    for (int j = 0; j < 16; ++j) {
        keys[j] = mono_key(sc[base + j]);
        atomicAdd(&hist[keys[j] >> 24], 1);
    }
    __syncthreads();

    if (tid == 0) {
        int acc = 0; int bbin = 255;
        for (; bbin >= 0; --bbin) {
            acc += hist[bbin];
            if (acc >= NCAND) break;
        }
        sBin1 = bbin;
        sAbove1 = acc - hist[bbin];
    }
    __syncthreads();
    const int bin1 = sBin1;
    const int above1 = sAbove1;
    hist[tid] = 0;
    __syncthreads();

    #pragma unroll
    for (int j = 0; j < 16; ++j) {
        if ((int)(keys[j] >> 24) == bin1)
            atomicAdd(&hist[(keys[j] >> 16) & 0xFF], 1);
    }
    __syncthreads();

    if (tid == 0) {
        int acc = above1; int bbin = 255;
        for (; bbin >= 0; --bbin) {
            acc += hist[bbin];
            if (acc >= NCAND) break;
        }
        sThresh16 = (bin1 << 8) | bbin;
    }
    __syncthreads();
    const uint32_t thresh16 = (uint32_t)sThresh16;

    #pragma unroll
    for (int j = 0; j < 16; ++j) {
        if ((keys[j] >> 16) >= thresh16) {
            int pos = atomicAdd(&sPCount, 1);
            if (pos < MAXPOOL) pooli[pos] = base + j;
        }
    }
    __syncthreads();
    const int pc = min(sPCount, MAXPOOL);

    const float* Kb = Km + (long long)b * SS * DD;
    for (int c = wid; c < pc; c += 8) {
        const int mi = pooli[c];
        const float* krow = Kb + (long long)mi * DD;
        double s = 0.0;
        #pragma unroll 8
        for (int i = 0; i < 32; ++i) {
            int d = lane + 32 * i;
            s += (double)qrow[d] * (double)krow[d];
        }
        #pragma unroll
        for (int off = 16; off > 0; off >>= 1)
            s += __shfl_xor_sync(0xffffffffu, s, off);
        if (lane == 0) cval[c] = s;
    }
    __syncthreads();

    if (tid < pc) {
        double v = cval[tid]; int ix = pooli[tid];
        int rank = 0;
        for (int j = 0; j < pc; ++j) {
            double vj = cval[j]; int ij = pooli[j];
            if (vj > v || (vj == v && ij < ix)) ++rank;
        }
        if (rank < TOPK) {
            selv[rank] = (float)(v * SCALE_D);
            seli[rank] = ix;
        }
    }
    __syncthreads();

    if (tid < 32) {
        float e = expf(selv[tid] - selv[0]);
        float s = e;
        #pragma unroll
        for (int off = 16; off > 0; off >>= 1)
            s += __shfl_xor_sync(0xffffffffu, s, off);
        prob[tid] = e / s;
    }
    __syncthreads();

    const float* Vb = V + (long long)b * SS * DD;
    const int d = tid * 4;
    float4 accv = make_float4(0.f, 0.f, 0.f, 0.f);
    #pragma unroll 4
    for (int i = 0; i < TOPK; ++i) {
        const float p = prob[i];
        float4 v = *(const float4*)(Vb + (long long)seli[i] * DD + d);
        accv.x = fmaf(p, v.x, accv.x);
        accv.y = fmaf(p, v.y, accv.y);
        accv.z = fmaf(p, v.z, accv.z);
        accv.w = fmaf(p, v.w, accv.w);
    }
    *(float4*)(ctx + (long long)r * DD + d) = accv;
}

// ---------------------------------------------------------------------------
// Launch
// ---------------------------------------------------------------------------
extern "C" void kernel_launch(void* const* d_in, const int* in_sizes, int n_in,
                              void* d_out, int out_size)
{
    const float* query = (const float*)d_in[0];
    const float* mem   = (const float*)d_in[1];
    const float* Wq = (const float*)d_in[3];
    const float* bq = (const float*)d_in[4];
    const float* Wk = (const float*)d_in[5];
    const float* bk = (const float*)d_in[6];
    const float* Wv = (const float*)d_in[7];
    const float* bv = (const float*)d_in[8];
    const float* Wo = (const float*)d_in[9];
    const float* bo = (const float*)d_in[10];
    float* out = (float*)d_out;

    float *Q, *K, *V, *S, *CTX;
    __nv_bfloat16 *Qh, *Kh, *Mh, *Ml, *Ch, *Cl, *Wh, *Wl;
    cudaGetSymbolAddress((void**)&Q,   g_Q);
    cudaGetSymbolAddress((void**)&K,   g_K);
    cudaGetSymbolAddress((void**)&V,   g_V);
    cudaGetSymbolAddress((void**)&S,   g_S);
    cudaGetSymbolAddress((void**)&CTX, g_CTX);
    cudaGetSymbolAddress((void**)&Qh,  g_Qh);
    cudaGetSymbolAddress((void**)&Kh,  g_Kh);
    cudaGetSymbolAddress((void**)&Mh,  g_Mh);
    cudaGetSymbolAddress((void**)&Ml,  g_Ml);
    cudaGetSymbolAddress((void**)&Ch,  g_Ch);
    cudaGetSymbolAddress((void**)&Cl,  g_Cl);
    cudaGetSymbolAddress((void**)&Wh,  g_Wh);
    cudaGetSymbolAddress((void**)&Wl,  g_Wl);

    const float inv_sqrt_d = 1.0f / 32.0f;

    // Q/K projections (fp32, FROZEN chain) with fused bf16 epilogue
    gemm_nt<<<dim3(DD / BN, MQ  / BM, 1), 256>>>(query, Wq, Q, Qh, bq, MQ,  DD, DD, 1.f, 0, 0, 0);
    gemm_nt<<<dim3(DD / BN, MKV / BM, 1), 256>>>(mem,   Wk, K, Kh, bk, MKV, DD, DD, 1.f, 0, 0, 0);

    // V projection via split-bf16 tensor cores (values only)
    f32_split_bf16_kernel<<<(MKV * DD / 4 + 255) / 256, 256>>>(mem, Mh, Ml, MKV * DD / 4);
    f32_split_bf16_kernel<<<(DD  * DD / 4 + 255) / 256, 256>>>(Wv,  Wh, Wl, DD  * DD / 4);
    gemm_nt_bf16_split<<<dim3(DD / 128, MKV / 128), 256>>>(Mh, Ml, Wh, Wl, V, bv);

    // Scores (candidate nomination): bf16 mma.sync
    gemm_nt_bf16_scores<<<dim3(SS / 128, TQ / 128, BATCH), 256>>>(Qh, Kh, S, inv_sqrt_d);

    // Histogram pool -> exact fp64 rescore -> top-32 -> softmax -> sparse AV
    topk_softmax_av<<<MQ, 256>>>(S, Q, K, V, CTX);

    // O projection via split-bf16 tensor cores (reuse weight split buffers)
    f32_split_bf16_kernel<<<(MQ * DD / 4 + 255) / 256, 256>>>(CTX, Ch, Cl, MQ * DD / 4);
    f32_split_bf16_kernel<<<(DD * DD / 4 + 255) / 256, 256>>>(Wo,  Wh, Wl, DD * DD / 4);
    gemm_nt_bf16_split<<<dim3(DD / 128, MQ / 128), 256>>>(Ch, Cl, Wh, Wl, out, bo);
}